// round 8
// baseline (speedup 1.0000x reference)
#include <cuda_runtime.h>
#include <cstdint>
#include <math.h>

#define BATCH 4096
#define N_GC  8192
#define N_PC  2048

#define TM 128
#define TN 128
#define KC 32                        // k floats per stage (128 B rows)
#define NCH (N_GC / KC)              // 256 chunks
#define STAGES 3
#define STAGE_BYTES ((TM + TN) * KC * 4)   // 32 KB
#define SMEM_SZ (STAGES * STAGE_BYTES)     // 96 KB

// -------- scratch (device globals: runtime alloc forbidden) ----------------
__device__ __align__(128) float g_Bt[(size_t)N_PC * N_GC];

// -------- helpers -----------------------------------------------------------
__device__ __forceinline__ float to_tf32(float x) {
    uint32_t r; asm("cvt.rna.tf32.f32 %0, %1;" : "=r"(r) : "f"(x));
    return __uint_as_float(r);
}
__device__ __forceinline__ uint32_t cvt_rna_u(uint32_t x) {
    uint32_t r; asm("cvt.rna.tf32.f32 %0, %1;" : "=r"(r) : "f"(__uint_as_float(x)));
    return r;
}
__device__ __forceinline__ float softplus_f(float x) {
    return fmaxf(x, 0.0f) + log1pf(expf(-fabsf(x)));
}
__device__ __forceinline__ uint32_t smem_u32(const void* p) {
    uint32_t a;
    asm("{ .reg .u64 t; cvta.to.shared.u64 t, %1; cvt.u32.u64 %0, t; }" : "=r"(a) : "l"(p));
    return a;
}
__device__ __forceinline__ void cp16(uint32_t dst, const void* src) {
    asm volatile("cp.async.cg.shared.global [%0], [%1], 16;" :: "r"(dst), "l"(src) : "memory");
}
__device__ __forceinline__ void cp_commit() { asm volatile("cp.async.commit_group;" ::: "memory"); }
template <int N> __device__ __forceinline__ void cp_wait() {
    asm volatile("cp.async.wait_group %0;" :: "n"(N) : "memory");
}
__device__ __forceinline__ void ldm4(uint32_t& r0, uint32_t& r1, uint32_t& r2, uint32_t& r3,
                                     uint32_t addr) {
    asm volatile("ldmatrix.sync.aligned.m8n8.x4.shared.b16 {%0,%1,%2,%3}, [%4];"
                 : "=r"(r0), "=r"(r1), "=r"(r2), "=r"(r3) : "r"(addr));
}
__device__ __forceinline__ void mma8(float* c, const uint32_t* a, uint32_t b0, uint32_t b1) {
    asm volatile(
        "mma.sync.aligned.m16n8k8.row.col.f32.tf32.tf32.f32 "
        "{%0,%1,%2,%3}, {%4,%5,%6,%7}, {%8,%9}, {%0,%1,%2,%3};"
        : "+f"(c[0]), "+f"(c[1]), "+f"(c[2]), "+f"(c[3])
        : "r"(a[0]), "r"(a[1]), "r"(a[2]), "r"(a[3]), "r"(b0), "r"(b1));
}

// -------- prologue: B = tf32(softplus(W) * mask) -----------------------------
__global__ void build_w_kernel(const float4* __restrict__ wr, const float4* __restrict__ mk) {
    size_t i = (size_t)blockIdx.x * blockDim.x + threadIdx.x;
    size_t stride = (size_t)gridDim.x * blockDim.x;
    float4* dst = reinterpret_cast<float4*>(g_Bt);
    const size_t n4 = (size_t)N_PC * N_GC / 4;
    for (size_t j = i; j < n4; j += stride) {
        float4 w = wr[j]; float4 m = mk[j]; float4 o;
        o.x = to_tf32(softplus_f(w.x) * m.x);
        o.y = to_tf32(softplus_f(w.y) * m.y);
        o.z = to_tf32(softplus_f(w.z) * m.z);
        o.w = to_tf32(softplus_f(w.w) * m.w);
        dst[j] = o;
    }
}

// -------- GEMM: C[4096,2048] = g * Bt^T, tf32 mma.sync, 64x64 warp tiles -----
// ks-loop software-pipelined with double-buffered fragments.
__global__ void __launch_bounds__(128, 2) purkinje_gemm(const float* __restrict__ g,
                                                        const float* __restrict__ b_pc,
                                                        float* __restrict__ out) {
    extern __shared__ char smem[];
    const uint32_t sb = smem_u32(smem);
    const int tid = threadIdx.x;
    const int wid = tid >> 5, l = tid & 31;
    const int n0 = blockIdx.x * TN;
    const int m0 = blockIdx.y * TM;
    const int wm = (wid & 1) * 64;       // warp m offset
    const int wn = (wid >> 1) * 64;      // warp n offset

    // ---- cp.async plan: 16 x 16B per thread per stage ----
    const int tr = tid >> 3, tc = tid & 7;
    const uint32_t dbase = (uint32_t)(tr * 128 + ((tc ^ (tr & 7)) * 16));
    const float* aptr = g    + (size_t)(m0 + tr) * N_GC + tc * 4;
    const float* bptr = g_Bt + (size_t)(n0 + tr) * N_GC + tc * 4;

    // ---- ldmatrix lane addressing ----
    const int arow   = (l & 7) | (l & 8);
    const int achunk = l >> 4;
    const int brow   = (l & 7) | ((l & 16) >> 1);
    const int bchunk = (l >> 3) & 1;
    uint32_t baseA[4], baseB[4];
    #pragma unroll
    for (int mt = 0; mt < 4; ++mt) baseA[mt] = (uint32_t)((wm + mt * 16 + arow) * 128);
    #pragma unroll
    for (int p = 0; p < 4; ++p)    baseB[p]  = (uint32_t)((TM + wn + p * 16 + brow) * 128);
    uint32_t chA[4], chB[4];
    #pragma unroll
    for (int ks = 0; ks < 4; ++ks) {
        chA[ks] = (uint32_t)(((ks * 2 + achunk) ^ (l & 7)) * 16);
        chB[ks] = (uint32_t)(((ks * 2 + bchunk) ^ (l & 7)) * 16);
    }

    float acc[4][8][4];
    #pragma unroll
    for (int i = 0; i < 4; ++i)
        #pragma unroll
        for (int j = 0; j < 8; ++j)
            #pragma unroll
            for (int q = 0; q < 4; ++q) acc[i][j][q] = 0.0f;

    // ---- prologue: stages 0,1 ----
    #pragma unroll
    for (int s = 0; s < STAGES - 1; ++s) {
        const uint32_t st = sb + s * STAGE_BYTES;
        const int koff = s * KC;
        #pragma unroll
        for (int j = 0; j < 8; ++j) {
            cp16(st + dbase + j * 2048,         aptr + koff + (size_t)j * 16 * N_GC);
            cp16(st + dbase + 16384 + j * 2048, bptr + koff + (size_t)j * 16 * N_GC);
        }
        cp_commit();
    }

    // double-buffered fragments
    uint32_t fa[2][4][4], fb[2][4][4];

    // ---- main loop ----
    for (int k = 0; k < NCH; ++k) {
        cp_wait<STAGES - 2>();
        __syncthreads();

        // issue next-chunk global prefetch first (fire-and-forget)
        if (k + STAGES - 1 < NCH) {
            const uint32_t stp = sb + ((k + STAGES - 1) % STAGES) * STAGE_BYTES;
            const int koff = (k + STAGES - 1) * KC;
            #pragma unroll
            for (int j = 0; j < 8; ++j) {
                cp16(stp + dbase + j * 2048,         aptr + koff + (size_t)j * 16 * N_GC);
                cp16(stp + dbase + 16384 + j * 2048, bptr + koff + (size_t)j * 16 * N_GC);
            }
        }
        cp_commit();

        const uint32_t st = sb + (k % STAGES) * STAGE_BYTES;

        // load fragments for ks=0 into buffer 0
        #pragma unroll
        for (int mt = 0; mt < 4; ++mt)
            ldm4(fa[0][mt][0], fa[0][mt][1], fa[0][mt][2], fa[0][mt][3], st + baseA[mt] + chA[0]);
        #pragma unroll
        for (int p = 0; p < 4; ++p)
            ldm4(fb[0][p][0], fb[0][p][1], fb[0][p][2], fb[0][p][3], st + baseB[p] + chB[0]);
        #pragma unroll
        for (int mt = 0; mt < 4; ++mt) {
            fa[0][mt][0] = cvt_rna_u(fa[0][mt][0]); fa[0][mt][1] = cvt_rna_u(fa[0][mt][1]);
            fa[0][mt][2] = cvt_rna_u(fa[0][mt][2]); fa[0][mt][3] = cvt_rna_u(fa[0][mt][3]);
        }

        #pragma unroll
        for (int ks = 0; ks < 4; ++ks) {
            const int cur = ks & 1, nxt = cur ^ 1;
            // prefetch fragments for ks+1 (overlaps with mma below)
            if (ks < 3) {
                #pragma unroll
                for (int mt = 0; mt < 4; ++mt)
                    ldm4(fa[nxt][mt][0], fa[nxt][mt][1], fa[nxt][mt][2], fa[nxt][mt][3],
                         st + baseA[mt] + chA[ks + 1]);
                #pragma unroll
                for (int p = 0; p < 4; ++p)
                    ldm4(fb[nxt][p][0], fb[nxt][p][1], fb[nxt][p][2], fb[nxt][p][3],
                         st + baseB[p] + chB[ks + 1]);
            }
            // mma on current buffer
            #pragma unroll
            for (int p = 0; p < 4; ++p) {
                #pragma unroll
                for (int mt = 0; mt < 4; ++mt) {
                    mma8(acc[mt][2 * p],     fa[cur][mt], fb[cur][p][0], fb[cur][p][1]);
                    mma8(acc[mt][2 * p + 1], fa[cur][mt], fb[cur][p][2], fb[cur][p][3]);
                }
            }
            // convert next A fragments after mma issue (off critical path)
            if (ks < 3) {
                #pragma unroll
                for (int mt = 0; mt < 4; ++mt) {
                    fa[nxt][mt][0] = cvt_rna_u(fa[nxt][mt][0]);
                    fa[nxt][mt][1] = cvt_rna_u(fa[nxt][mt][1]);
                    fa[nxt][mt][2] = cvt_rna_u(fa[nxt][mt][2]);
                    fa[nxt][mt][3] = cvt_rna_u(fa[nxt][mt][3]);
                }
            }
        }
    }

    // ---- epilogue: bias + relu ----
    #pragma unroll
    for (int mt = 0; mt < 4; ++mt) {
        const int row = m0 + wm + mt * 16 + (l >> 2);
        #pragma unroll
        for (int nt = 0; nt < 8; ++nt) {
            const int col = n0 + wn + nt * 8 + (l & 3) * 2;
            float2 bv = *reinterpret_cast<const float2*>(&b_pc[col]);
            float2 o0, o1;
            o0.x = fmaxf(acc[mt][nt][0] + bv.x, 0.0f);
            o0.y = fmaxf(acc[mt][nt][1] + bv.y, 0.0f);
            o1.x = fmaxf(acc[mt][nt][2] + bv.x, 0.0f);
            o1.y = fmaxf(acc[mt][nt][3] + bv.y, 0.0f);
            *reinterpret_cast<float2*>(&out[(size_t)row * N_PC + col])       = o0;
            *reinterpret_cast<float2*>(&out[(size_t)(row + 8) * N_PC + col]) = o1;
        }
    }
}

// -------- launch --------------------------------------------------------------
extern "C" void kernel_launch(void* const* d_in, const int* in_sizes, int n_in,
                              void* d_out, int out_size) {
    (void)in_sizes; (void)n_in; (void)out_size;
    cudaFuncSetAttribute(purkinje_gemm, cudaFuncAttributeMaxDynamicSharedMemorySize, SMEM_SZ);
    build_w_kernel<<<512, 256>>>(reinterpret_cast<const float4*>(d_in[1]),
                                 reinterpret_cast<const float4*>(d_in[3]));
    dim3 grid(N_PC / TN, BATCH / TM);
    purkinje_gemm<<<grid, 128, SMEM_SZ>>>(reinterpret_cast<const float*>(d_in[0]),
                                          reinterpret_cast<const float*>(d_in[2]),
                                          reinterpret_cast<float*>(d_out));
}

// round 9
// speedup vs baseline: 1.0543x; 1.0543x over previous
#include <cuda_runtime.h>
#include <cstdint>
#include <math.h>

#define BATCH 4096
#define N_GC  8192
#define N_PC  2048

#define TM 128
#define TN 128
#define KC 32                        // k floats per stage (128 B rows)
#define NCH (N_GC / KC)              // 256 chunks
#define STAGES 3
#define STAGE_BYTES ((TM + TN) * KC * 4)   // 32 KB
#define SOFF_TILE 1024
#define SMEM_SZ (SOFF_TILE + STAGES * STAGE_BYTES)   // 99328

// mbarrier layout in smem: full[0..2] @ 0,8,16 ; empty[0..2] @ 24,32,40
#define MB_FULL(s)  (sb + (s) * 8)
#define MB_EMPTY(s) (sb + 24 + (s) * 8)

// -------- scratch (device globals: runtime alloc forbidden) ----------------
__device__ __align__(128) float g_Bt[(size_t)N_PC * N_GC];

// -------- helpers -----------------------------------------------------------
__device__ __forceinline__ float to_tf32(float x) {
    uint32_t r; asm("cvt.rna.tf32.f32 %0, %1;" : "=r"(r) : "f"(x));
    return __uint_as_float(r);
}
__device__ __forceinline__ uint32_t cvt_rna_u(uint32_t x) {
    uint32_t r; asm("cvt.rna.tf32.f32 %0, %1;" : "=r"(r) : "f"(__uint_as_float(x)));
    return r;
}
__device__ __forceinline__ float softplus_f(float x) {
    return fmaxf(x, 0.0f) + log1pf(expf(-fabsf(x)));
}
__device__ __forceinline__ uint32_t smem_u32(const void* p) {
    uint32_t a;
    asm("{ .reg .u64 t; cvta.to.shared.u64 t, %1; cvt.u32.u64 %0, t; }" : "=r"(a) : "l"(p));
    return a;
}
__device__ __forceinline__ void cp16(uint32_t dst, const void* src) {
    asm volatile("cp.async.cg.shared.global [%0], [%1], 16;" :: "r"(dst), "l"(src) : "memory");
}
__device__ __forceinline__ void cp_mbar_arrive(uint32_t mbar) {
    asm volatile("cp.async.mbarrier.arrive.noinc.shared.b64 [%0];" :: "r"(mbar) : "memory");
}
__device__ __forceinline__ void mbar_init(uint32_t a, uint32_t c) {
    asm volatile("mbarrier.init.shared.b64 [%0], %1;" :: "r"(a), "r"(c) : "memory");
}
__device__ __forceinline__ void mbar_arrive(uint32_t a) {
    asm volatile("mbarrier.arrive.shared.b64 _, [%0];" :: "r"(a) : "memory");
}
__device__ __forceinline__ void mbar_wait(uint32_t a, uint32_t par) {
    asm volatile(
        "{ .reg .pred P;\nW%=:\n"
        "mbarrier.try_wait.parity.acquire.cta.shared::cta.b64 P, [%0], %1, 0x989680;\n"
        "@!P bra W%=;\n}"
        :: "r"(a), "r"(par) : "memory");
}
__device__ __forceinline__ void ldm4(uint32_t& r0, uint32_t& r1, uint32_t& r2, uint32_t& r3,
                                     uint32_t addr) {
    asm volatile("ldmatrix.sync.aligned.m8n8.x4.shared.b16 {%0,%1,%2,%3}, [%4];"
                 : "=r"(r0), "=r"(r1), "=r"(r2), "=r"(r3) : "r"(addr));
}
__device__ __forceinline__ void mma8(float* c, const uint32_t* a, uint32_t b0, uint32_t b1) {
    asm volatile(
        "mma.sync.aligned.m16n8k8.row.col.f32.tf32.tf32.f32 "
        "{%0,%1,%2,%3}, {%4,%5,%6,%7}, {%8,%9}, {%0,%1,%2,%3};"
        : "+f"(c[0]), "+f"(c[1]), "+f"(c[2]), "+f"(c[3])
        : "r"(a[0]), "r"(a[1]), "r"(a[2]), "r"(a[3]), "r"(b0), "r"(b1));
}

// -------- prologue: B = tf32(softplus(W) * mask) -----------------------------
__global__ void build_w_kernel(const float4* __restrict__ wr, const float4* __restrict__ mk) {
    size_t i = (size_t)blockIdx.x * blockDim.x + threadIdx.x;
    size_t stride = (size_t)gridDim.x * blockDim.x;
    float4* dst = reinterpret_cast<float4*>(g_Bt);
    const size_t n4 = (size_t)N_PC * N_GC / 4;
    for (size_t j = i; j < n4; j += stride) {
        float4 w = wr[j]; float4 m = mk[j]; float4 o;
        o.x = to_tf32(softplus_f(w.x) * m.x);
        o.y = to_tf32(softplus_f(w.y) * m.y);
        o.z = to_tf32(softplus_f(w.z) * m.z);
        o.w = to_tf32(softplus_f(w.w) * m.w);
        dst[j] = o;
    }
}

// -------- GEMM: C[4096,2048] = g * Bt^T, tf32 mma.sync, 64x64 warp tiles -----
// Barrier-free mbarrier full/empty pipeline: warps skew up to one chunk.
__global__ void __launch_bounds__(128, 2) purkinje_gemm(const float* __restrict__ g,
                                                        const float* __restrict__ b_pc,
                                                        float* __restrict__ out) {
    extern __shared__ char smem[];
    const uint32_t sb = smem_u32(smem);
    const int tid = threadIdx.x;
    const int wid = tid >> 5, l = tid & 31;
    const int n0 = blockIdx.x * TN;
    const int m0 = blockIdx.y * TM;
    const int wm = (wid & 1) * 64;       // warp m offset
    const int wn = (wid >> 1) * 64;      // warp n offset

    if (tid == 0) {
        #pragma unroll
        for (int s = 0; s < STAGES; ++s) { mbar_init(MB_FULL(s), 128); mbar_init(MB_EMPTY(s), 128); }
    }
    __syncthreads();

    // ---- cp.async plan: 16 x 16B per thread per stage ----
    const int tr = tid >> 3, tc = tid & 7;
    const uint32_t dbase = (uint32_t)(tr * 128 + ((tc ^ (tr & 7)) * 16));
    const float* aptr = g    + (size_t)(m0 + tr) * N_GC + tc * 4;
    const float* bptr = g_Bt + (size_t)(n0 + tr) * N_GC + tc * 4;

    // ---- ldmatrix lane addressing ----
    const int arow   = (l & 7) | (l & 8);
    const int achunk = l >> 4;
    const int brow   = (l & 7) | ((l & 16) >> 1);
    const int bchunk = (l >> 3) & 1;
    uint32_t baseA[4], baseB[4];
    #pragma unroll
    for (int mt = 0; mt < 4; ++mt) baseA[mt] = (uint32_t)(SOFF_TILE + (wm + mt * 16 + arow) * 128);
    #pragma unroll
    for (int p = 0; p < 4; ++p)    baseB[p]  = (uint32_t)(SOFF_TILE + (TM + wn + p * 16 + brow) * 128);
    uint32_t chA[4], chB[4];
    #pragma unroll
    for (int ks = 0; ks < 4; ++ks) {
        chA[ks] = (uint32_t)(((ks * 2 + achunk) ^ (l & 7)) * 16);
        chB[ks] = (uint32_t)(((ks * 2 + bchunk) ^ (l & 7)) * 16);
    }

    float acc[4][8][4];
    #pragma unroll
    for (int i = 0; i < 4; ++i)
        #pragma unroll
        for (int j = 0; j < 8; ++j)
            #pragma unroll
            for (int q = 0; q < 4; ++q) acc[i][j][q] = 0.0f;

    // ---- producer cursor (stage, phase=1 so first empty-waits pass) ----
    int pstage = 0; uint32_t pphase = 1;
    // prologue: produce chunks 0,1
    #pragma unroll
    for (int j = 0; j < 2; ++j) {
        mbar_wait(MB_EMPTY(pstage), pphase);     // passes immediately (phase=1)
        const uint32_t st = sb + SOFF_TILE + pstage * STAGE_BYTES;
        const int koff = j * KC;
        #pragma unroll
        for (int jj = 0; jj < 8; ++jj) {
            cp16(st + dbase + jj * 2048,         aptr + koff + (size_t)jj * 16 * N_GC);
            cp16(st + dbase + 16384 + jj * 2048, bptr + koff + (size_t)jj * 16 * N_GC);
        }
        cp_mbar_arrive(MB_FULL(pstage));
        if (++pstage == STAGES) { pstage = 0; pphase ^= 1; }
    }

    // ---- consumer cursor ----
    int cstage = 0; uint32_t cphase = 0;

    for (int k = 0; k < NCH; ++k) {
        // consume chunk k
        mbar_wait(MB_FULL(cstage), cphase);
        const uint32_t stb = (uint32_t)(cstage * STAGE_BYTES);
        #pragma unroll
        for (int ks = 0; ks < 4; ++ks) {
            uint32_t a[4][4], b[4][4];
            #pragma unroll
            for (int mt = 0; mt < 4; ++mt)
                ldm4(a[mt][0], a[mt][1], a[mt][2], a[mt][3], sb + stb + baseA[mt] + chA[ks]);
            #pragma unroll
            for (int p = 0; p < 4; ++p)
                ldm4(b[p][0], b[p][1], b[p][2], b[p][3], sb + stb + baseB[p] + chB[ks]);
            #pragma unroll
            for (int mt = 0; mt < 4; ++mt) {
                a[mt][0] = cvt_rna_u(a[mt][0]); a[mt][1] = cvt_rna_u(a[mt][1]);
                a[mt][2] = cvt_rna_u(a[mt][2]); a[mt][3] = cvt_rna_u(a[mt][3]);
            }
            if (ks == 3) mbar_arrive(MB_EMPTY(cstage));   // stage reads done
            #pragma unroll
            for (int p = 0; p < 4; ++p) {
                #pragma unroll
                for (int mt = 0; mt < 4; ++mt) {
                    mma8(acc[mt][2 * p],     a[mt], b[p][0], b[p][1]);
                    mma8(acc[mt][2 * p + 1], a[mt], b[p][2], b[p][3]);
                }
            }
        }
        if (++cstage == STAGES) { cstage = 0; cphase ^= 1; }

        // produce chunk k+2
        if (k + 2 < NCH) {
            mbar_wait(MB_EMPTY(pstage), pphase);
            const uint32_t st = sb + SOFF_TILE + pstage * STAGE_BYTES;
            const int koff = (k + 2) * KC;
            #pragma unroll
            for (int jj = 0; jj < 8; ++jj) {
                cp16(st + dbase + jj * 2048,         aptr + koff + (size_t)jj * 16 * N_GC);
                cp16(st + dbase + 16384 + jj * 2048, bptr + koff + (size_t)jj * 16 * N_GC);
            }
            cp_mbar_arrive(MB_FULL(pstage));
            if (++pstage == STAGES) { pstage = 0; pphase ^= 1; }
        }
    }

    // ---- epilogue: bias + relu ----
    #pragma unroll
    for (int mt = 0; mt < 4; ++mt) {
        const int row = m0 + wm + mt * 16 + (l >> 2);
        #pragma unroll
        for (int nt = 0; nt < 8; ++nt) {
            const int col = n0 + wn + nt * 8 + (l & 3) * 2;
            float2 bv = *reinterpret_cast<const float2*>(&b_pc[col]);
            float2 o0, o1;
            o0.x = fmaxf(acc[mt][nt][0] + bv.x, 0.0f);
            o0.y = fmaxf(acc[mt][nt][1] + bv.y, 0.0f);
            o1.x = fmaxf(acc[mt][nt][2] + bv.x, 0.0f);
            o1.y = fmaxf(acc[mt][nt][3] + bv.y, 0.0f);
            *reinterpret_cast<float2*>(&out[(size_t)row * N_PC + col])       = o0;
            *reinterpret_cast<float2*>(&out[(size_t)(row + 8) * N_PC + col]) = o1;
        }
    }
}

// -------- launch --------------------------------------------------------------
extern "C" void kernel_launch(void* const* d_in, const int* in_sizes, int n_in,
                              void* d_out, int out_size) {
    (void)in_sizes; (void)n_in; (void)out_size;
    cudaFuncSetAttribute(purkinje_gemm, cudaFuncAttributeMaxDynamicSharedMemorySize, SMEM_SZ);
    build_w_kernel<<<512, 256>>>(reinterpret_cast<const float4*>(d_in[1]),
                                 reinterpret_cast<const float4*>(d_in[3]));
    dim3 grid(N_PC / TN, BATCH / TM);
    purkinje_gemm<<<grid, 128, SMEM_SZ>>>(reinterpret_cast<const float*>(d_in[0]),
                                          reinterpret_cast<const float*>(d_in[2]),
                                          reinterpret_cast<float*>(d_out));
}

// round 10
// speedup vs baseline: 1.1744x; 1.1140x over previous
#include <cuda_runtime.h>
#include <cstdint>
#include <math.h>

#define BATCH 4096
#define N_GC  8192
#define N_PC  2048

#define TM 128
#define TN 128
#define KC 32                        // k floats per stage (128 B rows)
#define SPLITK 2
#define KHALF (N_GC / SPLITK)        // 4096
#define NCH (KHALF / KC)             // 128 chunks per split
#define STAGES 3
#define STAGE_BYTES ((TM + TN) * KC * 4)   // 32 KB
#define SOFF_TILE 1024
#define SMEM_SZ (SOFF_TILE + STAGES * STAGE_BYTES)   // 99328

#define MB_FULL(s)  (sb + (s) * 8)
#define MB_EMPTY(s) (sb + 24 + (s) * 8)

// -------- scratch (device globals: runtime alloc forbidden) ----------------
__device__ __align__(128) float g_Bt[(size_t)N_PC * N_GC];
__device__ __align__(128) float g_part[(size_t)SPLITK * BATCH * N_PC];

// -------- helpers -----------------------------------------------------------
__device__ __forceinline__ float to_tf32(float x) {
    uint32_t r; asm("cvt.rna.tf32.f32 %0, %1;" : "=r"(r) : "f"(x));
    return __uint_as_float(r);
}
__device__ __forceinline__ uint32_t cvt_rna_u(uint32_t x) {
    uint32_t r; asm("cvt.rna.tf32.f32 %0, %1;" : "=r"(r) : "f"(__uint_as_float(x)));
    return r;
}
__device__ __forceinline__ float softplus_f(float x) {
    return fmaxf(x, 0.0f) + log1pf(expf(-fabsf(x)));
}
__device__ __forceinline__ uint32_t smem_u32(const void* p) {
    uint32_t a;
    asm("{ .reg .u64 t; cvta.to.shared.u64 t, %1; cvt.u32.u64 %0, t; }" : "=r"(a) : "l"(p));
    return a;
}
__device__ __forceinline__ void cp16(uint32_t dst, const void* src) {
    asm volatile("cp.async.cg.shared.global [%0], [%1], 16;" :: "r"(dst), "l"(src) : "memory");
}
__device__ __forceinline__ void cp_mbar_arrive(uint32_t mbar) {
    asm volatile("cp.async.mbarrier.arrive.noinc.shared.b64 [%0];" :: "r"(mbar) : "memory");
}
__device__ __forceinline__ void mbar_init(uint32_t a, uint32_t c) {
    asm volatile("mbarrier.init.shared.b64 [%0], %1;" :: "r"(a), "r"(c) : "memory");
}
__device__ __forceinline__ void mbar_arrive(uint32_t a) {
    asm volatile("mbarrier.arrive.shared.b64 _, [%0];" :: "r"(a) : "memory");
}
__device__ __forceinline__ void mbar_wait(uint32_t a, uint32_t par) {
    asm volatile(
        "{ .reg .pred P;\nW%=:\n"
        "mbarrier.try_wait.parity.acquire.cta.shared::cta.b64 P, [%0], %1, 0x989680;\n"
        "@!P bra W%=;\n}"
        :: "r"(a), "r"(par) : "memory");
}
__device__ __forceinline__ void ldm4(uint32_t& r0, uint32_t& r1, uint32_t& r2, uint32_t& r3,
                                     uint32_t addr) {
    asm volatile("ldmatrix.sync.aligned.m8n8.x4.shared.b16 {%0,%1,%2,%3}, [%4];"
                 : "=r"(r0), "=r"(r1), "=r"(r2), "=r"(r3) : "r"(addr));
}
__device__ __forceinline__ void mma8(float* c, const uint32_t* a, uint32_t b0, uint32_t b1) {
    asm volatile(
        "mma.sync.aligned.m16n8k8.row.col.f32.tf32.tf32.f32 "
        "{%0,%1,%2,%3}, {%4,%5,%6,%7}, {%8,%9}, {%0,%1,%2,%3};"
        : "+f"(c[0]), "+f"(c[1]), "+f"(c[2]), "+f"(c[3])
        : "r"(a[0]), "r"(a[1]), "r"(a[2]), "r"(a[3]), "r"(b0), "r"(b1));
}

// -------- prologue: B = tf32(softplus(W) * mask) -----------------------------
__global__ void build_w_kernel(const float4* __restrict__ wr, const float4* __restrict__ mk) {
    size_t i = (size_t)blockIdx.x * blockDim.x + threadIdx.x;
    size_t stride = (size_t)gridDim.x * blockDim.x;
    float4* dst = reinterpret_cast<float4*>(g_Bt);
    const size_t n4 = (size_t)N_PC * N_GC / 4;
    for (size_t j = i; j < n4; j += stride) {
        float4 w = wr[j]; float4 m = mk[j]; float4 o;
        o.x = to_tf32(softplus_f(w.x) * m.x);
        o.y = to_tf32(softplus_f(w.y) * m.y);
        o.z = to_tf32(softplus_f(w.z) * m.z);
        o.w = to_tf32(softplus_f(w.w) * m.w);
        dst[j] = o;
    }
}

// -------- GEMM (split-K): part[z] = g[:, zK:] * Bt[:, zK:]^T -----------------
__global__ void __launch_bounds__(128, 2) purkinje_gemm(const float* __restrict__ g) {
    extern __shared__ char smem[];
    const uint32_t sb = smem_u32(smem);
    const int tid = threadIdx.x;
    const int wid = tid >> 5, l = tid & 31;
    const int n0 = blockIdx.x * TN;
    const int m0 = blockIdx.y * TM;
    const int kz = blockIdx.z * KHALF;     // K offset for this split
    const int wm = (wid & 1) * 64;
    const int wn = (wid >> 1) * 64;

    if (tid == 0) {
        #pragma unroll
        for (int s = 0; s < STAGES; ++s) { mbar_init(MB_FULL(s), 128); mbar_init(MB_EMPTY(s), 128); }
    }
    __syncthreads();

    // ---- cp.async plan: 16 x 16B per thread per stage ----
    const int tr = tid >> 3, tc = tid & 7;
    const uint32_t dbase = (uint32_t)(tr * 128 + ((tc ^ (tr & 7)) * 16));
    const float* aptr = g    + (size_t)(m0 + tr) * N_GC + kz + tc * 4;
    const float* bptr = g_Bt + (size_t)(n0 + tr) * N_GC + kz + tc * 4;

    // ---- ldmatrix lane addressing ----
    const int arow   = (l & 7) | (l & 8);
    const int achunk = l >> 4;
    const int brow   = (l & 7) | ((l & 16) >> 1);
    const int bchunk = (l >> 3) & 1;
    uint32_t baseA[4], baseB[4];
    #pragma unroll
    for (int mt = 0; mt < 4; ++mt) baseA[mt] = (uint32_t)(SOFF_TILE + (wm + mt * 16 + arow) * 128);
    #pragma unroll
    for (int p = 0; p < 4; ++p)    baseB[p]  = (uint32_t)(SOFF_TILE + (TM + wn + p * 16 + brow) * 128);
    uint32_t chA[4], chB[4];
    #pragma unroll
    for (int ks = 0; ks < 4; ++ks) {
        chA[ks] = (uint32_t)(((ks * 2 + achunk) ^ (l & 7)) * 16);
        chB[ks] = (uint32_t)(((ks * 2 + bchunk) ^ (l & 7)) * 16);
    }

    float acc[4][8][4];
    #pragma unroll
    for (int i = 0; i < 4; ++i)
        #pragma unroll
        for (int j = 0; j < 8; ++j)
            #pragma unroll
            for (int q = 0; q < 4; ++q) acc[i][j][q] = 0.0f;

    // ---- producer cursor ----
    int pstage = 0; uint32_t pphase = 1;
    #pragma unroll
    for (int j = 0; j < 2; ++j) {
        mbar_wait(MB_EMPTY(pstage), pphase);
        const uint32_t st = sb + SOFF_TILE + pstage * STAGE_BYTES;
        const int koff = j * KC;
        #pragma unroll
        for (int jj = 0; jj < 8; ++jj) {
            cp16(st + dbase + jj * 2048,         aptr + koff + (size_t)jj * 16 * N_GC);
            cp16(st + dbase + 16384 + jj * 2048, bptr + koff + (size_t)jj * 16 * N_GC);
        }
        cp_mbar_arrive(MB_FULL(pstage));
        if (++pstage == STAGES) { pstage = 0; pphase ^= 1; }
    }

    // ---- consumer cursor ----
    int cstage = 0; uint32_t cphase = 0;

    for (int k = 0; k < NCH; ++k) {
        mbar_wait(MB_FULL(cstage), cphase);
        const uint32_t stb = (uint32_t)(cstage * STAGE_BYTES);
        #pragma unroll
        for (int ks = 0; ks < 4; ++ks) {
            uint32_t a[4][4], b[4][4];
            #pragma unroll
            for (int mt = 0; mt < 4; ++mt)
                ldm4(a[mt][0], a[mt][1], a[mt][2], a[mt][3], sb + stb + baseA[mt] + chA[ks]);
            #pragma unroll
            for (int p = 0; p < 4; ++p)
                ldm4(b[p][0], b[p][1], b[p][2], b[p][3], sb + stb + baseB[p] + chB[ks]);
            #pragma unroll
            for (int mt = 0; mt < 4; ++mt) {
                a[mt][0] = cvt_rna_u(a[mt][0]); a[mt][1] = cvt_rna_u(a[mt][1]);
                a[mt][2] = cvt_rna_u(a[mt][2]); a[mt][3] = cvt_rna_u(a[mt][3]);
            }
            if (ks == 3) mbar_arrive(MB_EMPTY(cstage));
            #pragma unroll
            for (int p = 0; p < 4; ++p) {
                #pragma unroll
                for (int mt = 0; mt < 4; ++mt) {
                    mma8(acc[mt][2 * p],     a[mt], b[p][0], b[p][1]);
                    mma8(acc[mt][2 * p + 1], a[mt], b[p][2], b[p][3]);
                }
            }
        }
        if (++cstage == STAGES) { cstage = 0; cphase ^= 1; }

        if (k + 2 < NCH) {
            mbar_wait(MB_EMPTY(pstage), pphase);
            const uint32_t st = sb + SOFF_TILE + pstage * STAGE_BYTES;
            const int koff = (k + 2) * KC;
            #pragma unroll
            for (int jj = 0; jj < 8; ++jj) {
                cp16(st + dbase + jj * 2048,         aptr + koff + (size_t)jj * 16 * N_GC);
                cp16(st + dbase + 16384 + jj * 2048, bptr + koff + (size_t)jj * 16 * N_GC);
            }
            cp_mbar_arrive(MB_FULL(pstage));
            if (++pstage == STAGES) { pstage = 0; pphase ^= 1; }
        }
    }

    // ---- epilogue: store raw partials (bias/relu in reduce kernel) ----
    float* part = g_part + (size_t)blockIdx.z * BATCH * N_PC;
    #pragma unroll
    for (int mt = 0; mt < 4; ++mt) {
        const int row = m0 + wm + mt * 16 + (l >> 2);
        #pragma unroll
        for (int nt = 0; nt < 8; ++nt) {
            const int col = n0 + wn + nt * 8 + (l & 3) * 2;
            *reinterpret_cast<float2*>(&part[(size_t)row * N_PC + col]) =
                make_float2(acc[mt][nt][0], acc[mt][nt][1]);
            *reinterpret_cast<float2*>(&part[(size_t)(row + 8) * N_PC + col]) =
                make_float2(acc[mt][nt][2], acc[mt][nt][3]);
        }
    }
}

// -------- reduce: out = relu(p0 + p1 + bias) ---------------------------------
__global__ void reduce_kernel(const float* __restrict__ b_pc, float4* __restrict__ out) {
    const size_t n4 = (size_t)BATCH * N_PC / 4;
    const float4* p0 = reinterpret_cast<const float4*>(g_part);
    const float4* p1 = reinterpret_cast<const float4*>(g_part + (size_t)BATCH * N_PC);
    size_t i = (size_t)blockIdx.x * blockDim.x + threadIdx.x;
    size_t stride = (size_t)gridDim.x * blockDim.x;
    for (size_t j = i; j < n4; j += stride) {
        float4 a = p0[j], b = p1[j];
        const float4 bias = *reinterpret_cast<const float4*>(&b_pc[(j % (N_PC / 4)) * 4]);
        float4 o;
        o.x = fmaxf(a.x + b.x + bias.x, 0.0f);
        o.y = fmaxf(a.y + b.y + bias.y, 0.0f);
        o.z = fmaxf(a.z + b.z + bias.z, 0.0f);
        o.w = fmaxf(a.w + b.w + bias.w, 0.0f);
        out[j] = o;
    }
}

// -------- launch --------------------------------------------------------------
extern "C" void kernel_launch(void* const* d_in, const int* in_sizes, int n_in,
                              void* d_out, int out_size) {
    (void)in_sizes; (void)n_in; (void)out_size;
    cudaFuncSetAttribute(purkinje_gemm, cudaFuncAttributeMaxDynamicSharedMemorySize, SMEM_SZ);
    build_w_kernel<<<512, 256>>>(reinterpret_cast<const float4*>(d_in[1]),
                                 reinterpret_cast<const float4*>(d_in[3]));
    dim3 grid(N_PC / TN, BATCH / TM, SPLITK);
    purkinje_gemm<<<grid, 128, SMEM_SZ>>>(reinterpret_cast<const float*>(d_in[0]));
    reduce_kernel<<<2048, 256>>>(reinterpret_cast<const float*>(d_in[2]),
                                 reinterpret_cast<float4*>(d_out));
}

// round 11
// speedup vs baseline: 1.1800x; 1.0047x over previous
#include <cuda_runtime.h>
#include <cstdint>
#include <math.h>

#define BATCH 4096
#define N_GC  8192
#define N_PC  2048

#define TM 128
#define TN 128
#define KC 32                        // k floats per stage (128 B rows)
#define SPLITK 2
#define KHALF (N_GC / SPLITK)        // 4096
#define NCH (KHALF / KC)             // 128 chunks per tile
#define NTILES 1024                  // 32 m-tiles * 16 n-tiles * 2 z
#define GRID_P 296                   // 148 SMs * 2 CTAs
#define STAGES 3
#define STAGE_BYTES ((TM + TN) * KC * 4)   // 32 KB
#define SOFF_TILE 1024
#define SMEM_SZ (SOFF_TILE + STAGES * STAGE_BYTES)   // 99328

#define MB_FULL(s)  (sb + (s) * 8)
#define MB_EMPTY(s) (sb + 24 + (s) * 8)

// -------- scratch (device globals: runtime alloc forbidden) ----------------
__device__ __align__(128) float g_Bt[(size_t)N_PC * N_GC];
__device__ __align__(128) float g_part[(size_t)SPLITK * BATCH * N_PC];

// -------- helpers -----------------------------------------------------------
__device__ __forceinline__ float to_tf32(float x) {
    uint32_t r; asm("cvt.rna.tf32.f32 %0, %1;" : "=r"(r) : "f"(x));
    return __uint_as_float(r);
}
__device__ __forceinline__ uint32_t cvt_rna_u(uint32_t x) {
    uint32_t r; asm("cvt.rna.tf32.f32 %0, %1;" : "=r"(r) : "f"(__uint_as_float(x)));
    return r;
}
__device__ __forceinline__ float softplus_f(float x) {
    return fmaxf(x, 0.0f) + log1pf(expf(-fabsf(x)));
}
__device__ __forceinline__ uint32_t smem_u32(const void* p) {
    uint32_t a;
    asm("{ .reg .u64 t; cvta.to.shared.u64 t, %1; cvt.u32.u64 %0, t; }" : "=r"(a) : "l"(p));
    return a;
}
__device__ __forceinline__ void cp16(uint32_t dst, const void* src) {
    asm volatile("cp.async.cg.shared.global [%0], [%1], 16;" :: "r"(dst), "l"(src) : "memory");
}
__device__ __forceinline__ void cp_mbar_arrive(uint32_t mbar) {
    asm volatile("cp.async.mbarrier.arrive.noinc.shared.b64 [%0];" :: "r"(mbar) : "memory");
}
__device__ __forceinline__ void mbar_init(uint32_t a, uint32_t c) {
    asm volatile("mbarrier.init.shared.b64 [%0], %1;" :: "r"(a), "r"(c) : "memory");
}
__device__ __forceinline__ void mbar_arrive(uint32_t a) {
    asm volatile("mbarrier.arrive.shared.b64 _, [%0];" :: "r"(a) : "memory");
}
__device__ __forceinline__ void mbar_wait(uint32_t a, uint32_t par) {
    asm volatile(
        "{ .reg .pred P;\nW%=:\n"
        "mbarrier.try_wait.parity.acquire.cta.shared::cta.b64 P, [%0], %1, 0x989680;\n"
        "@!P bra W%=;\n}"
        :: "r"(a), "r"(par) : "memory");
}
__device__ __forceinline__ void mbar_wait_rlx(uint32_t a, uint32_t par) {
    asm volatile(
        "{ .reg .pred P;\nW%=:\n"
        "mbarrier.try_wait.parity.relaxed.cta.shared::cta.b64 P, [%0], %1, 0x989680;\n"
        "@!P bra W%=;\n}"
        :: "r"(a), "r"(par) : "memory");
}
__device__ __forceinline__ void ldm4(uint32_t& r0, uint32_t& r1, uint32_t& r2, uint32_t& r3,
                                     uint32_t addr) {
    asm volatile("ldmatrix.sync.aligned.m8n8.x4.shared.b16 {%0,%1,%2,%3}, [%4];"
                 : "=r"(r0), "=r"(r1), "=r"(r2), "=r"(r3) : "r"(addr));
}
__device__ __forceinline__ void mma8(float* c, const uint32_t* a, uint32_t b0, uint32_t b1) {
    asm volatile(
        "mma.sync.aligned.m16n8k8.row.col.f32.tf32.tf32.f32 "
        "{%0,%1,%2,%3}, {%4,%5,%6,%7}, {%8,%9}, {%0,%1,%2,%3};"
        : "+f"(c[0]), "+f"(c[1]), "+f"(c[2]), "+f"(c[3])
        : "r"(a[0]), "r"(a[1]), "r"(a[2]), "r"(a[3]), "r"(b0), "r"(b1));
}

// -------- prologue: B = tf32(softplus(W) * mask) -----------------------------
__global__ void build_w_kernel(const float4* __restrict__ wr, const float4* __restrict__ mk) {
    size_t i = (size_t)blockIdx.x * blockDim.x + threadIdx.x;
    size_t stride = (size_t)gridDim.x * blockDim.x;
    float4* dst = reinterpret_cast<float4*>(g_Bt);
    const size_t n4 = (size_t)N_PC * N_GC / 4;
    for (size_t j = i; j < n4; j += stride) {
        float4 w = wr[j]; float4 m = mk[j]; float4 o;
        o.x = to_tf32(softplus_f(w.x) * m.x);
        o.y = to_tf32(softplus_f(w.y) * m.y);
        o.z = to_tf32(softplus_f(w.z) * m.z);
        o.w = to_tf32(softplus_f(w.w) * m.w);
        dst[j] = o;
    }
}

// -------- persistent split-K GEMM --------------------------------------------
// tile t: z = t>>9, r = t&511, m_i = r>>4, n_i = r&15
__global__ void __launch_bounds__(128, 2) purkinje_gemm(const float* __restrict__ g) {
    extern __shared__ char smem[];
    const uint32_t sb = smem_u32(smem);
    const int tid = threadIdx.x;
    const int wid = tid >> 5, l = tid & 31;
    const int wm = (wid & 1) * 64;
    const int wn = (wid >> 1) * 64;

    if (tid == 0) {
        #pragma unroll
        for (int s = 0; s < STAGES; ++s) { mbar_init(MB_FULL(s), 128); mbar_init(MB_EMPTY(s), 128); }
    }
    __syncthreads();

    // ---- my tiles (static assignment, <=4) ----
    int my_tiles[4]; int ntile = 0;
    for (int t = blockIdx.x; t < NTILES; t += GRID_P) my_tiles[ntile++] = t;
    const int nchunks = ntile * NCH;

    // ---- cp.async per-thread geometry ----
    const int tr = tid >> 3, tc = tid & 7;
    const uint32_t dbase = (uint32_t)(tr * 128 + ((tc ^ (tr & 7)) * 16));

    // ---- ldmatrix lane addressing ----
    const int arow   = (l & 7) | (l & 8);
    const int achunk = l >> 4;
    const int brow   = (l & 7) | ((l & 16) >> 1);
    const int bchunk = (l >> 3) & 1;
    uint32_t baseA[4], baseB[4];
    #pragma unroll
    for (int mt = 0; mt < 4; ++mt) baseA[mt] = (uint32_t)(SOFF_TILE + (wm + mt * 16 + arow) * 128);
    #pragma unroll
    for (int p = 0; p < 4; ++p)    baseB[p]  = (uint32_t)(SOFF_TILE + (TM + wn + p * 16 + brow) * 128);
    uint32_t chA[4], chB[4];
    #pragma unroll
    for (int ks = 0; ks < 4; ++ks) {
        chA[ks] = (uint32_t)(((ks * 2 + achunk) ^ (l & 7)) * 16);
        chB[ks] = (uint32_t)(((ks * 2 + bchunk) ^ (l & 7)) * 16);
    }

    float acc[4][8][4];
    #pragma unroll
    for (int i = 0; i < 4; ++i)
        #pragma unroll
        for (int j = 0; j < 8; ++j)
            #pragma unroll
            for (int q = 0; q < 4; ++q) acc[i][j][q] = 0.0f;

    // ---- producer closure: produce flat chunk pc into stage pstage ----
    int pstage = 0; uint32_t pphase = 1;
    int cstage = 0; uint32_t cphase = 0;

    // prologue: produce flat chunks 0,1
    #pragma unroll
    for (int pc0 = 0; pc0 < 2; ++pc0) {
        mbar_wait_rlx(MB_EMPTY(pstage), pphase);      // passes immediately
        const int t = my_tiles[pc0 >> 7];             // pc0<2 -> tile 0
        const int z = t >> 9, r = t & 511, m_i = r >> 4, n_i = r & 15;
        const int kb = z * KHALF + (pc0 & 127) * KC + tc * 4;
        const float* ap = g    + (size_t)(m_i * TM + tr) * N_GC + kb;
        const float* bp = g_Bt + (size_t)(n_i * TN + tr) * N_GC + kb;
        const uint32_t st = sb + SOFF_TILE + pstage * STAGE_BYTES;
        #pragma unroll
        for (int jj = 0; jj < 8; ++jj) {
            cp16(st + dbase + jj * 2048,         ap + (size_t)jj * 16 * N_GC);
            cp16(st + dbase + 16384 + jj * 2048, bp + (size_t)jj * 16 * N_GC);
        }
        cp_mbar_arrive(MB_FULL(pstage));
        if (++pstage == STAGES) { pstage = 0; pphase ^= 1; }
    }
    int pc = 2;

    for (int w = 0; w < ntile; ++w) {
        for (int k = 0; k < NCH; ++k) {
            // consume
            mbar_wait(MB_FULL(cstage), cphase);
            const uint32_t stb = (uint32_t)(cstage * STAGE_BYTES);
            #pragma unroll
            for (int ks = 0; ks < 4; ++ks) {
                uint32_t a[4][4], b[4][4];
                #pragma unroll
                for (int mt = 0; mt < 4; ++mt)
                    ldm4(a[mt][0], a[mt][1], a[mt][2], a[mt][3], sb + stb + baseA[mt] + chA[ks]);
                #pragma unroll
                for (int p = 0; p < 4; ++p)
                    ldm4(b[p][0], b[p][1], b[p][2], b[p][3], sb + stb + baseB[p] + chB[ks]);
                #pragma unroll
                for (int mt = 0; mt < 4; ++mt) {
                    a[mt][0] = cvt_rna_u(a[mt][0]); a[mt][1] = cvt_rna_u(a[mt][1]);
                    a[mt][2] = cvt_rna_u(a[mt][2]); a[mt][3] = cvt_rna_u(a[mt][3]);
                }
                if (ks == 3) mbar_arrive(MB_EMPTY(cstage));
                #pragma unroll
                for (int p = 0; p < 4; ++p) {
                    #pragma unroll
                    for (int mt = 0; mt < 4; ++mt) {
                        mma8(acc[mt][2 * p],     a[mt], b[p][0], b[p][1]);
                        mma8(acc[mt][2 * p + 1], a[mt], b[p][2], b[p][3]);
                    }
                }
            }
            if (++cstage == STAGES) { cstage = 0; cphase ^= 1; }

            // produce flat chunk pc (may belong to next tile)
            if (pc < nchunks) {
                mbar_wait_rlx(MB_EMPTY(pstage), pphase);
                const int t = my_tiles[pc >> 7];
                const int z = t >> 9, r = t & 511, m_i = r >> 4, n_i = r & 15;
                const int kb = z * KHALF + (pc & 127) * KC + tc * 4;
                const float* ap = g    + (size_t)(m_i * TM + tr) * N_GC + kb;
                const float* bp = g_Bt + (size_t)(n_i * TN + tr) * N_GC + kb;
                const uint32_t st = sb + SOFF_TILE + pstage * STAGE_BYTES;
                #pragma unroll
                for (int jj = 0; jj < 8; ++jj) {
                    cp16(st + dbase + jj * 2048,         ap + (size_t)jj * 16 * N_GC);
                    cp16(st + dbase + 16384 + jj * 2048, bp + (size_t)jj * 16 * N_GC);
                }
                cp_mbar_arrive(MB_FULL(pstage));
                if (++pstage == STAGES) { pstage = 0; pphase ^= 1; }
                ++pc;
            }
        }

        // ---- epilogue for tile w: store raw partials, reset acc ----
        {
            const int t = my_tiles[w];
            const int z = t >> 9, r = t & 511, m_i = r >> 4, n_i = r & 15;
            float* part = g_part + (size_t)z * BATCH * N_PC;
            const int m0 = m_i * TM, n0 = n_i * TN;
            #pragma unroll
            for (int mt = 0; mt < 4; ++mt) {
                const int row = m0 + wm + mt * 16 + (l >> 2);
                #pragma unroll
                for (int nt = 0; nt < 8; ++nt) {
                    const int col = n0 + wn + nt * 8 + (l & 3) * 2;
                    *reinterpret_cast<float2*>(&part[(size_t)row * N_PC + col]) =
                        make_float2(acc[mt][nt][0], acc[mt][nt][1]);
                    *reinterpret_cast<float2*>(&part[(size_t)(row + 8) * N_PC + col]) =
                        make_float2(acc[mt][nt][2], acc[mt][nt][3]);
                    acc[mt][nt][0] = 0.0f; acc[mt][nt][1] = 0.0f;
                    acc[mt][nt][2] = 0.0f; acc[mt][nt][3] = 0.0f;
                }
            }
        }
    }
}

// -------- reduce: out = relu(p0 + p1 + bias) ---------------------------------
__global__ void reduce_kernel(const float* __restrict__ b_pc, float4* __restrict__ out) {
    const size_t n4 = (size_t)BATCH * N_PC / 4;
    const float4* p0 = reinterpret_cast<const float4*>(g_part);
    const float4* p1 = reinterpret_cast<const float4*>(g_part + (size_t)BATCH * N_PC);
    size_t i = (size_t)blockIdx.x * blockDim.x + threadIdx.x;
    size_t stride = (size_t)gridDim.x * blockDim.x;
    for (size_t j = i; j < n4; j += stride) {
        float4 a = p0[j], b = p1[j];
        const float4 bias = *reinterpret_cast<const float4*>(&b_pc[(j % (N_PC / 4)) * 4]);
        float4 o;
        o.x = fmaxf(a.x + b.x + bias.x, 0.0f);
        o.y = fmaxf(a.y + b.y + bias.y, 0.0f);
        o.z = fmaxf(a.z + b.z + bias.z, 0.0f);
        o.w = fmaxf(a.w + b.w + bias.w, 0.0f);
        out[j] = o;
    }
}

// -------- launch --------------------------------------------------------------
extern "C" void kernel_launch(void* const* d_in, const int* in_sizes, int n_in,
                              void* d_out, int out_size) {
    (void)in_sizes; (void)n_in; (void)out_size;
    cudaFuncSetAttribute(purkinje_gemm, cudaFuncAttributeMaxDynamicSharedMemorySize, SMEM_SZ);
    build_w_kernel<<<2048, 256>>>(reinterpret_cast<const float4*>(d_in[1]),
                                  reinterpret_cast<const float4*>(d_in[3]));
    purkinje_gemm<<<GRID_P, 128, SMEM_SZ>>>(reinterpret_cast<const float*>(d_in[0]));
    reduce_kernel<<<4096, 256>>>(reinterpret_cast<const float*>(d_in[2]),
                                 reinterpret_cast<float4*>(d_out));
}